// round 9
// baseline (speedup 1.0000x reference)
#include <cuda_runtime.h>
#include <cuda_fp16.h>

#define FOUT 64
#define KTOT 256
#define NMAX 100000
#define EMAX 3200000
#define TROWS 128
#define KC 32
#define SCAN_B 1024
#define NB ((NMAX + SCAN_B - 1) / SCAN_B)   // 98 blocks

// ---------------- scratch (device globals) ----------------
__device__ __align__(256) __half g_hh[NMAX * FOUT]; // 12.8 MB: h = xW (fp16, gather copy)
__device__ __align__(256) int    g_src[EMAX];       // 12.8 MB: src ids sorted by dst
__device__ int   g_cnt[NMAX];
__device__ int   g_off[NMAX + 1];
__device__ int   g_bsum[NB];
__device__ int   g_bbase[NB];
__device__ float g_asrc[NMAX];
__device__ float g_adst[NMAX];

#define FMA2(acc, w, xv) \
    asm("fma.rn.f32x2 %0, %1, %2, %0;" : "+l"(acc) : "l"(w), "l"(xv))

// ---------------- kernel 1: zero counters ----------------
__global__ void zero_cnt(int n) {
    int i = blockIdx.x * blockDim.x + threadIdx.x;
    if (i < n) g_cnt[i] = 0;
}

// ---------------- kernel 2: histogram of dst (4 edges/thread, int4) ----------------
__global__ void hist_kernel(const int* __restrict__ ei, int e) {
    int g = blockIdx.x * blockDim.x + threadIdx.x;   // quad index
    int nq = e >> 2;
    if (g < nq) {
        int4 d = reinterpret_cast<const int4*>(ei + e)[g];
        atomicAdd(&g_cnt[d.x], 1);
        atomicAdd(&g_cnt[d.y], 1);
        atomicAdd(&g_cnt[d.z], 1);
        atomicAdd(&g_cnt[d.w], 1);
    } else {
        // tail (e not multiple of 4)
        int base = nq * 4 + (g - nq);
        if (base < e && g - nq < 4) atomicAdd(&g_cnt[ei[e + base]], 1);
    }
}

// ---------------- scan phase 1: per-block sums ----------------
__global__ __launch_bounds__(SCAN_B) void scan_p1(int n) {
    __shared__ int wsum[32];
    int i = blockIdx.x * SCAN_B + threadIdx.x;
    int c = (i < n) ? g_cnt[i] : 0;
    int lane = threadIdx.x & 31, wid = threadIdx.x >> 5;
    int v = c;
#pragma unroll
    for (int o = 16; o > 0; o >>= 1) v += __shfl_xor_sync(0xffffffffu, v, o);
    if (lane == 0) wsum[wid] = v;
    __syncthreads();
    if (wid == 0) {
        int w = wsum[lane];
#pragma unroll
        for (int o = 16; o > 0; o >>= 1) w += __shfl_xor_sync(0xffffffffu, w, o);
        if (lane == 0) g_bsum[blockIdx.x] = w;
    }
}

// ---------------- scan phase 2: scan the NB block sums (1 block) ----------------
__global__ __launch_bounds__(128) void scan_p2(int n, int e) {
    __shared__ int wpre[4];
    int tid = threadIdx.x;
    int lane = tid & 31, wid = tid >> 5;
    int s = (tid < NB) ? g_bsum[tid] : 0;
    int v = s;
#pragma unroll
    for (int o = 1; o < 32; o <<= 1) {
        int t = __shfl_up_sync(0xffffffffu, v, o);
        if (lane >= o) v += t;
    }
    if (lane == 31) wpre[wid] = v;
    __syncthreads();
    if (tid == 0) {
        int a = 0;
#pragma unroll
        for (int k = 0; k < 4; k++) { int t = wpre[k]; wpre[k] = a; a += t; }
    }
    __syncthreads();
    if (tid < NB) g_bbase[tid] = v - s + wpre[wid];
    if (tid == 0) g_off[n] = e;
}

// ---------------- scan phase 3: local scan + base, write offsets/cursors ----------------
__global__ __launch_bounds__(SCAN_B) void scan_p3(int n) {
    __shared__ int wsum[32];
    int i = blockIdx.x * SCAN_B + threadIdx.x;
    int c = (i < n) ? g_cnt[i] : 0;
    int lane = threadIdx.x & 31, wid = threadIdx.x >> 5;
    int v = c;
#pragma unroll
    for (int o = 1; o < 32; o <<= 1) {
        int t = __shfl_up_sync(0xffffffffu, v, o);
        if (lane >= o) v += t;
    }
    if (lane == 31) wsum[wid] = v;
    __syncthreads();
    if (wid == 0) {
        int w = wsum[lane];
#pragma unroll
        for (int o = 1; o < 32; o <<= 1) {
            int t = __shfl_up_sync(0xffffffffu, w, o);
            if (lane >= o) w += t;
        }
        wsum[lane] = w;
    }
    __syncthreads();
    int excl = v - c + (wid > 0 ? wsum[wid - 1] : 0);
    int off = g_bbase[blockIdx.x] + excl;
    if (i < n) { g_off[i] = off; g_cnt[i] = off; }
}

// ---------------- kernel 4: scatter src ids (4 edges/thread, int4) ----------------
__global__ void scatter_kernel(const int* __restrict__ ei, int e) {
    int g = blockIdx.x * blockDim.x + threadIdx.x;
    int nq = e >> 2;
    if (g < nq) {
        int4 s = reinterpret_cast<const int4*>(ei)[g];
        int4 d = reinterpret_cast<const int4*>(ei + e)[g];
        int p0 = atomicAdd(&g_cnt[d.x], 1);
        int p1 = atomicAdd(&g_cnt[d.y], 1);
        int p2 = atomicAdd(&g_cnt[d.z], 1);
        int p3 = atomicAdd(&g_cnt[d.w], 1);
        g_src[p0] = s.x;
        g_src[p1] = s.y;
        g_src[p2] = s.z;
        g_src[p3] = s.w;
    } else {
        int base = nq * 4 + (g - nq);
        if (base < e && g - nq < 4) {
            int pos = atomicAdd(&g_cnt[ei[e + base]], 1);
            g_src[pos] = ei[base];
        }
    }
}

// ---------------- kernel 5: GEMM h = x@W (FFMA2 packed) + attention halves ----------------
__global__ __launch_bounds__(256) void gemm_kernel(
    const float* __restrict__ x, const float* __restrict__ W,
    const float* __restrict__ att_src, const float* __restrict__ att_dst, int n)
{
    __shared__ float xs[TROWS][KC + 1];
    __shared__ float ws[KC][FOUT];

    int tid = threadIdx.x;
    int tx = tid & 7;
    int ty = tid >> 3;
    int row0 = blockIdx.x * TROWS;

    unsigned long long accp[4][4];
#pragma unroll
    for (int r = 0; r < 4; r++)
#pragma unroll
        for (int c = 0; c < 4; c++) accp[r][c] = 0ull;

    for (int k0 = 0; k0 < KTOT; k0 += KC) {
#pragma unroll
        for (int i = 0; i < 2; i++) {
            int kk = (tid >> 4) + i * 16;
            int cc = (tid & 15) * 4;
            *reinterpret_cast<float4*>(&ws[kk][cc]) =
                *reinterpret_cast<const float4*>(&W[(k0 + kk) * FOUT + cc]);
        }
        {
            int lr = tid >> 3;
            int kq = (tid & 7) * 4;
#pragma unroll
            for (int i = 0; i < 4; i++) {
                int row = row0 + lr + i * 32;
                float4 v = make_float4(0.f, 0.f, 0.f, 0.f);
                if (row < n)
                    v = *reinterpret_cast<const float4*>(&x[row * KTOT + k0 + kq]);
                xs[lr + i * 32][kq + 0] = v.x;
                xs[lr + i * 32][kq + 1] = v.y;
                xs[lr + i * 32][kq + 2] = v.z;
                xs[lr + i * 32][kq + 3] = v.w;
            }
        }
        __syncthreads();
#pragma unroll
        for (int k = 0; k < KC; k++) {
            ulonglong2 w01 = *reinterpret_cast<const ulonglong2*>(&ws[k][tx * 8]);
            ulonglong2 w23 = *reinterpret_cast<const ulonglong2*>(&ws[k][tx * 8 + 4]);
#pragma unroll
            for (int r = 0; r < 4; r++) {
                unsigned xu = __float_as_uint(xs[ty * 4 + r][k]);
                unsigned long long xd;
                asm("mov.b64 %0, {%1, %1};" : "=l"(xd) : "r"(xu));
                FMA2(accp[r][0], w01.x, xd);
                FMA2(accp[r][1], w01.y, xd);
                FMA2(accp[r][2], w23.x, xd);
                FMA2(accp[r][3], w23.y, xd);
            }
        }
        __syncthreads();
    }

    float4 as0 = *reinterpret_cast<const float4*>(&att_src[tx * 8]);
    float4 as1 = *reinterpret_cast<const float4*>(&att_src[tx * 8 + 4]);
    float4 ad0 = *reinterpret_cast<const float4*>(&att_dst[tx * 8]);
    float4 ad1 = *reinterpret_cast<const float4*>(&att_dst[tx * 8 + 4]);
    float as[8] = {as0.x, as0.y, as0.z, as0.w, as1.x, as1.y, as1.z, as1.w};
    float ad[8] = {ad0.x, ad0.y, ad0.z, ad0.w, ad1.x, ad1.y, ad1.z, ad1.w};

#pragma unroll
    for (int r = 0; r < 4; r++) {
        int row = row0 + ty * 4 + r;
        float a[8];
#pragma unroll
        for (int c = 0; c < 4; c++)
            asm("mov.b64 {%0, %1}, %2;" : "=f"(a[2 * c]), "=f"(a[2 * c + 1]) : "l"(accp[r][c]));

        float ps = 0.f, pd = 0.f;
#pragma unroll
        for (int j = 0; j < 8; j++) { ps += a[j] * as[j]; pd += a[j] * ad[j]; }
#pragma unroll
        for (int o = 1; o < 8; o <<= 1) {
            ps += __shfl_xor_sync(0xffffffffu, ps, o);
            pd += __shfl_xor_sync(0xffffffffu, pd, o);
        }
        if (row < n) {
            __half2 p0 = __float22half2_rn(make_float2(a[0], a[1]));
            __half2 p1 = __float22half2_rn(make_float2(a[2], a[3]));
            __half2 p2 = __float22half2_rn(make_float2(a[4], a[5]));
            __half2 p3 = __float22half2_rn(make_float2(a[6], a[7]));
            uint4 st;
            st.x = *reinterpret_cast<unsigned*>(&p0);
            st.y = *reinterpret_cast<unsigned*>(&p1);
            st.z = *reinterpret_cast<unsigned*>(&p2);
            st.w = *reinterpret_cast<unsigned*>(&p3);
            *reinterpret_cast<uint4*>(&g_hh[row * FOUT + tx * 8]) = st;
            if (tx == 0) { g_asrc[row] = ps; g_adst[row] = pd; }
        }
    }
}

// ---------------- kernel 6: gather aggregation, 4 edges in flight per warp ----------------
// 8 lanes x 16B (uint4 of 8 halves) cover one 64-col fp16 row; quarter-warps q=0..3
// each own edge t = q mod 4. No max-subtraction (ratio-invariant; logits are small).
__global__ __launch_bounds__(256) void aggregate_kernel(
    float* __restrict__ out, const float* __restrict__ bias, int n)
{
    __shared__ int   s_s[8][32];
    __shared__ float p_s[8][32];

    int w = threadIdx.x >> 5;
    int lane = threadIdx.x & 31;
    int q = lane >> 3;      // quarter 0..3
    int l8 = lane & 7;      // column-group within row
    int node = blockIdx.x * 8 + w;
    if (node >= n) return;

    int rs = g_off[node];
    int re = g_off[node + 1];
    float adst = g_adst[node];

    float acc[8];
#pragma unroll
    for (int j = 0; j < 8; j++) acc[j] = 0.f;
    float dsum = 0.f;

    for (int base = rs; base < re; base += 32) {
        int cnt = min(32, re - base);
        int s = 0;
        float p = 0.f;
        if (lane < cnt) {
            s = g_src[base + lane];
            float v = g_asrc[s] + adst;
            v = v > 0.f ? v : 0.2f * v;
            p = __expf(v);
        }
        dsum += p;
        s_s[w][lane] = s;
        p_s[w][lane] = p;
        __syncwarp();
#pragma unroll 2
        for (int t = q; t < cnt; t += 4) {
            int st = s_s[w][t];
            float pt = p_s[w][t];
            uint4 hv = *reinterpret_cast<const uint4*>(&g_hh[(size_t)st * FOUT + l8 * 8]);
            float2 f0 = __half22float2(*reinterpret_cast<__half2*>(&hv.x));
            float2 f1 = __half22float2(*reinterpret_cast<__half2*>(&hv.y));
            float2 f2 = __half22float2(*reinterpret_cast<__half2*>(&hv.z));
            float2 f3 = __half22float2(*reinterpret_cast<__half2*>(&hv.w));
            acc[0] += pt * f0.x; acc[1] += pt * f0.y;
            acc[2] += pt * f1.x; acc[3] += pt * f1.y;
            acc[4] += pt * f2.x; acc[5] += pt * f2.y;
            acc[6] += pt * f3.x; acc[7] += pt * f3.y;
        }
        __syncwarp();
    }

    // self-loop (quarter 0 covers the full row; p counted once via lane==0)
    if (q == 0) {
        float v = g_asrc[node] + adst;
        v = v > 0.f ? v : 0.2f * v;
        float p = __expf(v);
        if (lane == 0) dsum += p;
        uint4 hv = *reinterpret_cast<const uint4*>(&g_hh[(size_t)node * FOUT + l8 * 8]);
        float2 f0 = __half22float2(*reinterpret_cast<__half2*>(&hv.x));
        float2 f1 = __half22float2(*reinterpret_cast<__half2*>(&hv.y));
        float2 f2 = __half22float2(*reinterpret_cast<__half2*>(&hv.z));
        float2 f3 = __half22float2(*reinterpret_cast<__half2*>(&hv.w));
        acc[0] += p * f0.x; acc[1] += p * f0.y;
        acc[2] += p * f1.x; acc[3] += p * f1.y;
        acc[4] += p * f2.x; acc[5] += p * f2.y;
        acc[6] += p * f3.x; acc[7] += p * f3.y;
    }

    // denom: full-warp reduce
#pragma unroll
    for (int o = 16; o > 0; o >>= 1)
        dsum += __shfl_xor_sync(0xffffffffu, dsum, o);

    // combine quarters: q0 += q2, q1 += q3 (offset 16), then q0 += q1 (offset 8)
#pragma unroll
    for (int j = 0; j < 8; j++) {
        acc[j] += __shfl_down_sync(0xffffffffu, acc[j], 16);
        acc[j] += __shfl_down_sync(0xffffffffu, acc[j], 8);
    }

    if (q == 0) {
        float inv = 1.0f / (dsum + 1e-16f);
        const float4* b4 = reinterpret_cast<const float4*>(bias);
        float4 b0 = b4[l8 * 2], b1 = b4[l8 * 2 + 1];
        float4* o4 = reinterpret_cast<float4*>(out) + (size_t)node * 16 + l8 * 2;
        o4[0] = make_float4(acc[0] * inv + b0.x, acc[1] * inv + b0.y,
                            acc[2] * inv + b0.z, acc[3] * inv + b0.w);
        o4[1] = make_float4(acc[4] * inv + b1.x, acc[5] * inv + b1.y,
                            acc[6] * inv + b1.z, acc[7] * inv + b1.w);
    }
}

// ---------------- launch: fork CSR build ∥ GEMM, join before aggregate ----------------
extern "C" void kernel_launch(void* const* d_in, const int* in_sizes, int n_in,
                              void* d_out, int out_size) {
    const float* x       = (const float*)d_in[0];
    const int*   ei      = (const int*)d_in[1];
    const float* W       = (const float*)d_in[2];
    const float* att_src = (const float*)d_in[3];
    const float* att_dst = (const float*)d_in[4];
    const float* bias    = (const float*)d_in[5];
    float* out = (float*)d_out;

    int n = in_sizes[0] / KTOT;   // 100000
    int e = in_sizes[1] / 2;      // 3200000

    static cudaStream_t s2 = nullptr;
    static cudaEvent_t evFork = nullptr, evJoin = nullptr;
    if (s2 == nullptr) {
        cudaStreamCreateWithFlags(&s2, cudaStreamNonBlocking);
        cudaEventCreateWithFlags(&evFork, cudaEventDisableTiming);
        cudaEventCreateWithFlags(&evJoin, cudaEventDisableTiming);
    }

    // fork: GEMM on side stream, CSR build on origin stream
    cudaEventRecord(evFork, 0);
    cudaStreamWaitEvent(s2, evFork, 0);
    gemm_kernel<<<(n + TROWS - 1) / TROWS, 256, 0, s2>>>(x, W, att_src, att_dst, n);
    cudaEventRecord(evJoin, s2);

    int nq = e / 4 + 4;  // quads + tail threads
    zero_cnt<<<(n + 255) / 256, 256>>>(n);
    hist_kernel<<<(nq + 255) / 256, 256>>>(ei, e);
    scan_p1<<<NB, SCAN_B>>>(n);
    scan_p2<<<1, 128>>>(n, e);
    scan_p3<<<NB, SCAN_B>>>(n);
    scatter_kernel<<<(nq + 255) / 256, 256>>>(ei, e);

    cudaStreamWaitEvent(0, evJoin, 0);

    aggregate_kernel<<<(n + 7) / 8, 256>>>(out, bias, n);
}

// round 10
// speedup vs baseline: 1.4522x; 1.4522x over previous
#include <cuda_runtime.h>
#include <cuda_fp16.h>

#define FOUT 64
#define KTOT 256
#define NMAX 100000
#define EMAX 3200000
#define SCAN_B 1024
#define NB ((NMAX + SCAN_B - 1) / SCAN_B)   // 98 blocks
#define GB_ROWS 128

// ---------------- scratch (device globals) ----------------
__device__ __align__(256) __half g_hh[NMAX * FOUT]; // 12.8 MB: h = xW (fp16)
__device__ __align__(256) int    g_src[EMAX];       // 12.8 MB: src ids sorted by dst
__device__ int   g_cnt[NMAX];
__device__ int   g_off[NMAX + 1];
__device__ int   g_bsum[NB];
__device__ int   g_bbase[NB];
__device__ float g_asrc[NMAX];
__device__ float g_adst[NMAX];

// ---------------- kernel 1: zero counters ----------------
__global__ void zero_cnt(int n) {
    int i = blockIdx.x * blockDim.x + threadIdx.x;
    if (i < n) g_cnt[i] = 0;
}

// ---------------- kernel 2: histogram of dst (4 edges/thread) ----------------
__global__ void hist_kernel(const int* __restrict__ ei, int e) {
    int g = blockIdx.x * blockDim.x + threadIdx.x;
    int nq = e >> 2;
    if (g < nq) {
        int4 d = reinterpret_cast<const int4*>(ei + e)[g];
        atomicAdd(&g_cnt[d.x], 1);
        atomicAdd(&g_cnt[d.y], 1);
        atomicAdd(&g_cnt[d.z], 1);
        atomicAdd(&g_cnt[d.w], 1);
    } else {
        int base = nq * 4 + (g - nq);
        if (base < e && g - nq < 4) atomicAdd(&g_cnt[ei[e + base]], 1);
    }
}

// ---------------- scan phase 1 ----------------
__global__ __launch_bounds__(SCAN_B) void scan_p1(int n) {
    __shared__ int wsum[32];
    int i = blockIdx.x * SCAN_B + threadIdx.x;
    int c = (i < n) ? g_cnt[i] : 0;
    int lane = threadIdx.x & 31, wid = threadIdx.x >> 5;
    int v = c;
#pragma unroll
    for (int o = 16; o > 0; o >>= 1) v += __shfl_xor_sync(0xffffffffu, v, o);
    if (lane == 0) wsum[wid] = v;
    __syncthreads();
    if (wid == 0) {
        int w = wsum[lane];
#pragma unroll
        for (int o = 16; o > 0; o >>= 1) w += __shfl_xor_sync(0xffffffffu, w, o);
        if (lane == 0) g_bsum[blockIdx.x] = w;
    }
}

// ---------------- scan phase 2 ----------------
__global__ __launch_bounds__(128) void scan_p2(int n, int e) {
    __shared__ int wpre[4];
    int tid = threadIdx.x;
    int lane = tid & 31, wid = tid >> 5;
    int s = (tid < NB) ? g_bsum[tid] : 0;
    int v = s;
#pragma unroll
    for (int o = 1; o < 32; o <<= 1) {
        int t = __shfl_up_sync(0xffffffffu, v, o);
        if (lane >= o) v += t;
    }
    if (lane == 31) wpre[wid] = v;
    __syncthreads();
    if (tid == 0) {
        int a = 0;
#pragma unroll
        for (int k = 0; k < 4; k++) { int t = wpre[k]; wpre[k] = a; a += t; }
    }
    __syncthreads();
    if (tid < NB) g_bbase[tid] = v - s + wpre[wid];
    if (tid == 0) g_off[n] = e;
}

// ---------------- scan phase 3 ----------------
__global__ __launch_bounds__(SCAN_B) void scan_p3(int n) {
    __shared__ int wsum[32];
    int i = blockIdx.x * SCAN_B + threadIdx.x;
    int c = (i < n) ? g_cnt[i] : 0;
    int lane = threadIdx.x & 31, wid = threadIdx.x >> 5;
    int v = c;
#pragma unroll
    for (int o = 1; o < 32; o <<= 1) {
        int t = __shfl_up_sync(0xffffffffu, v, o);
        if (lane >= o) v += t;
    }
    if (lane == 31) wsum[wid] = v;
    __syncthreads();
    if (wid == 0) {
        int w = wsum[lane];
#pragma unroll
        for (int o = 1; o < 32; o <<= 1) {
            int t = __shfl_up_sync(0xffffffffu, w, o);
            if (lane >= o) w += t;
        }
        wsum[lane] = w;
    }
    __syncthreads();
    int excl = v - c + (wid > 0 ? wsum[wid - 1] : 0);
    int off = g_bbase[blockIdx.x] + excl;
    if (i < n) { g_off[i] = off; g_cnt[i] = off; }
}

// ---------------- kernel 4: scatter src ids (4 edges/thread) ----------------
__global__ void scatter_kernel(const int* __restrict__ ei, int e) {
    int g = blockIdx.x * blockDim.x + threadIdx.x;
    int nq = e >> 2;
    if (g < nq) {
        int4 s = reinterpret_cast<const int4*>(ei)[g];
        int4 d = reinterpret_cast<const int4*>(ei + e)[g];
        int p0 = atomicAdd(&g_cnt[d.x], 1);
        int p1 = atomicAdd(&g_cnt[d.y], 1);
        int p2 = atomicAdd(&g_cnt[d.z], 1);
        int p3 = atomicAdd(&g_cnt[d.w], 1);
        g_src[p0] = s.x;
        g_src[p1] = s.y;
        g_src[p2] = s.z;
        g_src[p3] = s.w;
    } else {
        int base = nq * 4 + (g - nq);
        if (base < e && g - nq < 4) {
            int pos = atomicAdd(&g_cnt[ei[e + base]], 1);
            g_src[pos] = ei[base];
        }
    }
}

// ---------------- kernel 5: tensor-core GEMM (tf32 mma.m16n8k8) ----------------
// Block: 256 threads (8 warps) x 128-row tile. Warp w owns rows w*16..w*16+15.
// K-chunks of 32; per chunk: stage x(128x32) and W(32x64) as tf32 bits in smem.
__global__ __launch_bounds__(256) void gemm_tc(
    const float* __restrict__ x, const float* __restrict__ W,
    const float* __restrict__ att_src, const float* __restrict__ att_dst, int n)
{
    __shared__ unsigned xs[GB_ROWS][36];  // pad 36: banks (4g+c) conflict-free
    __shared__ unsigned ws[32][72];       // pad 72: banks (8c+g) conflict-free

    int tid = threadIdx.x;
    int lane = tid & 31;
    int w = tid >> 5;
    int g = lane >> 2;   // groupID (row within fragment)
    int c = lane & 3;    // threadID in group
    int row0 = blockIdx.x * GB_ROWS;
    int wrow = w * 16;

    float d[8][4];
#pragma unroll
    for (int nt = 0; nt < 8; nt++)
#pragma unroll
        for (int j = 0; j < 4; j++) d[nt][j] = 0.f;

    for (int k0 = 0; k0 < KTOT; k0 += 32) {
        // stage x chunk: 1024 float4s, 4 per thread
#pragma unroll
        for (int i = 0; i < 4; i++) {
            int idx = tid + i * 256;
            int r = idx >> 3;
            int cc = (idx & 7) * 4;
            float4 v = make_float4(0.f, 0.f, 0.f, 0.f);
            if (row0 + r < n)
                v = *reinterpret_cast<const float4*>(&x[(size_t)(row0 + r) * KTOT + k0 + cc]);
            uint4 u;
            asm("cvt.rna.tf32.f32 %0, %1;" : "=r"(u.x) : "f"(v.x));
            asm("cvt.rna.tf32.f32 %0, %1;" : "=r"(u.y) : "f"(v.y));
            asm("cvt.rna.tf32.f32 %0, %1;" : "=r"(u.z) : "f"(v.z));
            asm("cvt.rna.tf32.f32 %0, %1;" : "=r"(u.w) : "f"(v.w));
            *reinterpret_cast<uint4*>(&xs[r][cc]) = u;
        }
        // stage W chunk: 512 float4s, 2 per thread
#pragma unroll
        for (int i = 0; i < 2; i++) {
            int idx = tid + i * 256;
            int r = idx >> 4;
            int cc = (idx & 15) * 4;
            float4 v = *reinterpret_cast<const float4*>(&W[(size_t)(k0 + r) * FOUT + cc]);
            uint4 u;
            asm("cvt.rna.tf32.f32 %0, %1;" : "=r"(u.x) : "f"(v.x));
            asm("cvt.rna.tf32.f32 %0, %1;" : "=r"(u.y) : "f"(v.y));
            asm("cvt.rna.tf32.f32 %0, %1;" : "=r"(u.z) : "f"(v.z));
            asm("cvt.rna.tf32.f32 %0, %1;" : "=r"(u.w) : "f"(v.w));
            *reinterpret_cast<uint4*>(&ws[r][cc]) = u;
        }
        __syncthreads();

#pragma unroll
        for (int ks = 0; ks < 4; ks++) {
            unsigned a0 = xs[wrow + g][ks * 8 + c];
            unsigned a1 = xs[wrow + g + 8][ks * 8 + c];
            unsigned a2 = xs[wrow + g][ks * 8 + c + 4];
            unsigned a3 = xs[wrow + g + 8][ks * 8 + c + 4];
#pragma unroll
            for (int nt = 0; nt < 8; nt++) {
                unsigned b0 = ws[ks * 8 + c][nt * 8 + g];
                unsigned b1 = ws[ks * 8 + c + 4][nt * 8 + g];
                asm("mma.sync.aligned.m16n8k8.row.col.f32.tf32.tf32.f32 "
                    "{%0,%1,%2,%3}, {%4,%5,%6,%7}, {%8,%9}, {%0,%1,%2,%3};"
                    : "+f"(d[nt][0]), "+f"(d[nt][1]), "+f"(d[nt][2]), "+f"(d[nt][3])
                    : "r"(a0), "r"(a1), "r"(a2), "r"(a3), "r"(b0), "r"(b1));
            }
        }
        __syncthreads();
    }

    // epilogue: rows r1 = row0+wrow+g (d0,d1), r2 = r1+8 (d2,d3); thread owns cols nt*8+2c,+1
    float as_v[16], ad_v[16];
#pragma unroll
    for (int nt = 0; nt < 8; nt++) {
        as_v[nt * 2 + 0] = att_src[nt * 8 + 2 * c + 0];
        as_v[nt * 2 + 1] = att_src[nt * 8 + 2 * c + 1];
        ad_v[nt * 2 + 0] = att_dst[nt * 8 + 2 * c + 0];
        ad_v[nt * 2 + 1] = att_dst[nt * 8 + 2 * c + 1];
    }

    float ps1 = 0.f, pd1 = 0.f, ps2 = 0.f, pd2 = 0.f;
#pragma unroll
    for (int nt = 0; nt < 8; nt++) {
        ps1 += d[nt][0] * as_v[2 * nt] + d[nt][1] * as_v[2 * nt + 1];
        pd1 += d[nt][0] * ad_v[2 * nt] + d[nt][1] * ad_v[2 * nt + 1];
        ps2 += d[nt][2] * as_v[2 * nt] + d[nt][3] * as_v[2 * nt + 1];
        pd2 += d[nt][2] * ad_v[2 * nt] + d[nt][3] * ad_v[2 * nt + 1];
    }
    // reduce over the 4 lanes of each group (c = lane&3)
#pragma unroll
    for (int o = 1; o < 4; o <<= 1) {
        ps1 += __shfl_xor_sync(0xffffffffu, ps1, o);
        pd1 += __shfl_xor_sync(0xffffffffu, pd1, o);
        ps2 += __shfl_xor_sync(0xffffffffu, ps2, o);
        pd2 += __shfl_xor_sync(0xffffffffu, pd2, o);
    }

    int r1 = row0 + wrow + g;
    int r2 = r1 + 8;
    if (c == 0) {
        if (r1 < n) { g_asrc[r1] = ps1; g_adst[r1] = pd1; }
        if (r2 < n) { g_asrc[r2] = ps2; g_adst[r2] = pd2; }
    }
    if (r1 < n) {
#pragma unroll
        for (int nt = 0; nt < 8; nt++) {
            __half2 h = __float22half2_rn(make_float2(d[nt][0], d[nt][1]));
            *reinterpret_cast<__half2*>(&g_hh[(size_t)r1 * FOUT + nt * 8 + 2 * c]) = h;
        }
    }
    if (r2 < n) {
#pragma unroll
        for (int nt = 0; nt < 8; nt++) {
            __half2 h = __float22half2_rn(make_float2(d[nt][2], d[nt][3]));
            *reinterpret_cast<__half2*>(&g_hh[(size_t)r2 * FOUT + nt * 8 + 2 * c]) = h;
        }
    }
}

// ---------------- kernel 6: gather aggregation (R7 best: half-warp, fp16 h) ----------------
__global__ __launch_bounds__(256) void aggregate_kernel(
    float* __restrict__ out, const float* __restrict__ bias, int n)
{
    __shared__ int   s_s[8][32];
    __shared__ float p_s[8][32];

    int w = threadIdx.x >> 5;
    int lane = threadIdx.x & 31;
    int half = lane >> 4;
    int l = lane & 15;
    int node = blockIdx.x * 8 + w;
    if (node >= n) return;

    int rs = g_off[node];
    int re = g_off[node + 1];
    float adst = g_adst[node];

    float4 acc = make_float4(0.f, 0.f, 0.f, 0.f);
    float dsum = 0.f;

    for (int base = rs; base < re; base += 32) {
        int cnt = min(32, re - base);
        int s = 0;
        float p = 0.f;
        if (lane < cnt) {
            s = g_src[base + lane];
            float v = g_asrc[s] + adst;
            v = v > 0.f ? v : 0.2f * v;
            p = __expf(v);
        }
        dsum += p;
        s_s[w][lane] = s;
        p_s[w][lane] = p;
        __syncwarp();
#pragma unroll 4
        for (int t = half; t < cnt; t += 2) {
            int st = s_s[w][t];
            float pt = p_s[w][t];
            uint2 hv = *reinterpret_cast<const uint2*>(&g_hh[(size_t)st * FOUT + l * 4]);
            float2 f01 = __half22float2(*reinterpret_cast<__half2*>(&hv.x));
            float2 f23 = __half22float2(*reinterpret_cast<__half2*>(&hv.y));
            acc.x += pt * f01.x; acc.y += pt * f01.y;
            acc.z += pt * f23.x; acc.w += pt * f23.y;
        }
        __syncwarp();
    }

    if (half == 0) {
        float v = g_asrc[node] + adst;
        v = v > 0.f ? v : 0.2f * v;
        float p = __expf(v);
        if (l == 0) dsum += p;
        uint2 hv = *reinterpret_cast<const uint2*>(&g_hh[(size_t)node * FOUT + l * 4]);
        float2 f01 = __half22float2(*reinterpret_cast<__half2*>(&hv.x));
        float2 f23 = __half22float2(*reinterpret_cast<__half2*>(&hv.y));
        acc.x += p * f01.x; acc.y += p * f01.y;
        acc.z += p * f23.x; acc.w += p * f23.y;
    }

#pragma unroll
    for (int o = 16; o > 0; o >>= 1)
        dsum += __shfl_xor_sync(0xffffffffu, dsum, o);

    acc.x += __shfl_down_sync(0xffffffffu, acc.x, 16);
    acc.y += __shfl_down_sync(0xffffffffu, acc.y, 16);
    acc.z += __shfl_down_sync(0xffffffffu, acc.z, 16);
    acc.w += __shfl_down_sync(0xffffffffu, acc.w, 16);

    if (half == 0) {
        float inv = 1.0f / (dsum + 1e-16f);
        float4 b = reinterpret_cast<const float4*>(bias)[l];
        reinterpret_cast<float4*>(out)[(size_t)node * 16 + l] =
            make_float4(acc.x * inv + b.x, acc.y * inv + b.y,
                        acc.z * inv + b.z, acc.w * inv + b.w);
    }
}

// ---------------- launch: fork GEMM ∥ CSR build, join before aggregate ----------------
extern "C" void kernel_launch(void* const* d_in, const int* in_sizes, int n_in,
                              void* d_out, int out_size) {
    const float* x       = (const float*)d_in[0];
    const int*   ei      = (const int*)d_in[1];
    const float* W       = (const float*)d_in[2];
    const float* att_src = (const float*)d_in[3];
    const float* att_dst = (const float*)d_in[4];
    const float* bias    = (const float*)d_in[5];
    float* out = (float*)d_out;

    int n = in_sizes[0] / KTOT;   // 100000
    int e = in_sizes[1] / 2;      // 3200000

    static cudaStream_t s2 = nullptr;
    static cudaEvent_t evFork = nullptr, evJoin = nullptr;
    if (s2 == nullptr) {
        cudaStreamCreateWithFlags(&s2, cudaStreamNonBlocking);
        cudaEventCreateWithFlags(&evFork, cudaEventDisableTiming);
        cudaEventCreateWithFlags(&evJoin, cudaEventDisableTiming);
    }

    cudaEventRecord(evFork, 0);
    cudaStreamWaitEvent(s2, evFork, 0);
    gemm_tc<<<(n + GB_ROWS - 1) / GB_ROWS, 256, 0, s2>>>(x, W, att_src, att_dst, n);
    cudaEventRecord(evJoin, s2);

    int nq = e / 4 + 4;
    zero_cnt<<<(n + 255) / 256, 256>>>(n);
    hist_kernel<<<(nq + 255) / 256, 256>>>(ei, e);
    scan_p1<<<NB, SCAN_B>>>(n);
    scan_p2<<<1, 128>>>(n, e);
    scan_p3<<<NB, SCAN_B>>>(n);
    scatter_kernel<<<(nq + 255) / 256, 256>>>(ei, e);

    cudaStreamWaitEvent(0, evJoin, 0);

    aggregate_kernel<<<(n + 7) / 8, 256>>>(out, bias, n);
}

// round 11
// speedup vs baseline: 1.5356x; 1.0575x over previous
#include <cuda_runtime.h>
#include <cuda_fp16.h>

#define FOUT 64
#define KTOT 256
#define NMAX 100000
#define EMAX 3200000
#define SCAN_B 1024
#define NB ((NMAX + SCAN_B - 1) / SCAN_B)   // 98 blocks
#define GB_ROWS 128

// ---------------- scratch (device globals) ----------------
__device__ __align__(256) __half g_hh[NMAX * FOUT]; // 12.8 MB: h = xW (fp16)
__device__ __align__(256) int    g_src[EMAX + 32];  // src ids sorted by dst (+pad, zero-init)
__device__ int   g_cnt[NMAX];
__device__ int   g_off[NMAX + 1];
__device__ int   g_bsum[NB];
__device__ float g_asrc[NMAX];
__device__ float g_adst[NMAX];

// ---------------- kernel 1: zero counters (+ set g_off[n]=e) ----------------
__global__ void zero_cnt(int n, int e) {
    int i = blockIdx.x * blockDim.x + threadIdx.x;
    if (i < n) g_cnt[i] = 0;
    if (i == 0) g_off[n] = e;
}

// ---------------- kernel 2: histogram of dst (4 edges/thread) ----------------
__global__ void hist_kernel(const int* __restrict__ ei, int e) {
    int g = blockIdx.x * blockDim.x + threadIdx.x;
    int nq = e >> 2;
    if (g < nq) {
        int4 d = reinterpret_cast<const int4*>(ei + e)[g];
        atomicAdd(&g_cnt[d.x], 1);
        atomicAdd(&g_cnt[d.y], 1);
        atomicAdd(&g_cnt[d.z], 1);
        atomicAdd(&g_cnt[d.w], 1);
    } else {
        int base = nq * 4 + (g - nq);
        if (base < e && g - nq < 4) atomicAdd(&g_cnt[ei[e + base]], 1);
    }
}

// ---------------- scan phase 1: per-block sums ----------------
__global__ __launch_bounds__(SCAN_B) void scan_p1(int n) {
    __shared__ int wsum[32];
    int i = blockIdx.x * SCAN_B + threadIdx.x;
    int c = (i < n) ? g_cnt[i] : 0;
    int lane = threadIdx.x & 31, wid = threadIdx.x >> 5;
    int v = c;
#pragma unroll
    for (int o = 16; o > 0; o >>= 1) v += __shfl_xor_sync(0xffffffffu, v, o);
    if (lane == 0) wsum[wid] = v;
    __syncthreads();
    if (wid == 0) {
        int w = wsum[lane];
#pragma unroll
        for (int o = 16; o > 0; o >>= 1) w += __shfl_xor_sync(0xffffffffu, w, o);
        if (lane == 0) g_bsum[blockIdx.x] = w;
    }
}

// ---------------- scan phase 3 (merged p2): block base from g_bsum + local scan ----------------
__global__ __launch_bounds__(SCAN_B) void scan_p3(int n) {
    __shared__ int wsum[32];
    __shared__ int sbase;
    int tid = threadIdx.x;
    int lane = tid & 31, wid = tid >> 5;

    // warp 0: exclusive prefix of block sums for this block
    if (wid == 0) {
        int v = 0;
        for (int j = lane; j < NB; j += 32)
            if (j < blockIdx.x) v += g_bsum[j];
#pragma unroll
        for (int o = 16; o > 0; o >>= 1) v += __shfl_xor_sync(0xffffffffu, v, o);
        if (lane == 0) sbase = v;
    }

    int i = blockIdx.x * SCAN_B + tid;
    int c = (i < n) ? g_cnt[i] : 0;
    int v = c;
#pragma unroll
    for (int o = 1; o < 32; o <<= 1) {
        int t = __shfl_up_sync(0xffffffffu, v, o);
        if (lane >= o) v += t;
    }
    if (lane == 31) wsum[wid] = v;
    __syncthreads();
    if (wid == 0) {
        int w = wsum[lane];
#pragma unroll
        for (int o = 1; o < 32; o <<= 1) {
            int t = __shfl_up_sync(0xffffffffu, w, o);
            if (lane >= o) w += t;
        }
        wsum[lane] = w;
    }
    __syncthreads();
    int excl = v - c + (wid > 0 ? wsum[wid - 1] : 0);
    int off = sbase + excl;
    if (i < n) { g_off[i] = off; g_cnt[i] = off; }
}

// ---------------- kernel 4: scatter src ids (4 edges/thread) ----------------
__global__ void scatter_kernel(const int* __restrict__ ei, int e) {
    int g = blockIdx.x * blockDim.x + threadIdx.x;
    int nq = e >> 2;
    if (g < nq) {
        int4 s = reinterpret_cast<const int4*>(ei)[g];
        int4 d = reinterpret_cast<const int4*>(ei + e)[g];
        int p0 = atomicAdd(&g_cnt[d.x], 1);
        int p1 = atomicAdd(&g_cnt[d.y], 1);
        int p2 = atomicAdd(&g_cnt[d.z], 1);
        int p3 = atomicAdd(&g_cnt[d.w], 1);
        g_src[p0] = s.x;
        g_src[p1] = s.y;
        g_src[p2] = s.z;
        g_src[p3] = s.w;
    } else {
        int base = nq * 4 + (g - nq);
        if (base < e && g - nq < 4) {
            int pos = atomicAdd(&g_cnt[ei[e + base]], 1);
            g_src[pos] = ei[base];
        }
    }
}

// ---------------- kernel 5: tensor-core GEMM (tf32 mma.m16n8k8) ----------------
__global__ __launch_bounds__(256) void gemm_tc(
    const float* __restrict__ x, const float* __restrict__ W,
    const float* __restrict__ att_src, const float* __restrict__ att_dst, int n)
{
    __shared__ unsigned xs[GB_ROWS][36];
    __shared__ unsigned ws[32][72];

    int tid = threadIdx.x;
    int lane = tid & 31;
    int w = tid >> 5;
    int g = lane >> 2;
    int c = lane & 3;
    int row0 = blockIdx.x * GB_ROWS;
    int wrow = w * 16;

    float d[8][4];
#pragma unroll
    for (int nt = 0; nt < 8; nt++)
#pragma unroll
        for (int j = 0; j < 4; j++) d[nt][j] = 0.f;

    for (int k0 = 0; k0 < KTOT; k0 += 32) {
#pragma unroll
        for (int i = 0; i < 4; i++) {
            int idx = tid + i * 256;
            int r = idx >> 3;
            int cc = (idx & 7) * 4;
            float4 v = make_float4(0.f, 0.f, 0.f, 0.f);
            if (row0 + r < n)
                v = *reinterpret_cast<const float4*>(&x[(size_t)(row0 + r) * KTOT + k0 + cc]);
            uint4 u;
            asm("cvt.rna.tf32.f32 %0, %1;" : "=r"(u.x) : "f"(v.x));
            asm("cvt.rna.tf32.f32 %0, %1;" : "=r"(u.y) : "f"(v.y));
            asm("cvt.rna.tf32.f32 %0, %1;" : "=r"(u.z) : "f"(v.z));
            asm("cvt.rna.tf32.f32 %0, %1;" : "=r"(u.w) : "f"(v.w));
            *reinterpret_cast<uint4*>(&xs[r][cc]) = u;
        }
#pragma unroll
        for (int i = 0; i < 2; i++) {
            int idx = tid + i * 256;
            int r = idx >> 4;
            int cc = (idx & 15) * 4;
            float4 v = *reinterpret_cast<const float4*>(&W[(size_t)(k0 + r) * FOUT + cc]);
            uint4 u;
            asm("cvt.rna.tf32.f32 %0, %1;" : "=r"(u.x) : "f"(v.x));
            asm("cvt.rna.tf32.f32 %0, %1;" : "=r"(u.y) : "f"(v.y));
            asm("cvt.rna.tf32.f32 %0, %1;" : "=r"(u.z) : "f"(v.z));
            asm("cvt.rna.tf32.f32 %0, %1;" : "=r"(u.w) : "f"(v.w));
            *reinterpret_cast<uint4*>(&ws[r][cc]) = u;
        }
        __syncthreads();

#pragma unroll
        for (int ks = 0; ks < 4; ks++) {
            unsigned a0 = xs[wrow + g][ks * 8 + c];
            unsigned a1 = xs[wrow + g + 8][ks * 8 + c];
            unsigned a2 = xs[wrow + g][ks * 8 + c + 4];
            unsigned a3 = xs[wrow + g + 8][ks * 8 + c + 4];
#pragma unroll
            for (int nt = 0; nt < 8; nt++) {
                unsigned b0 = ws[ks * 8 + c][nt * 8 + g];
                unsigned b1 = ws[ks * 8 + c + 4][nt * 8 + g];
                asm("mma.sync.aligned.m16n8k8.row.col.f32.tf32.tf32.f32 "
                    "{%0,%1,%2,%3}, {%4,%5,%6,%7}, {%8,%9}, {%0,%1,%2,%3};"
                    : "+f"(d[nt][0]), "+f"(d[nt][1]), "+f"(d[nt][2]), "+f"(d[nt][3])
                    : "r"(a0), "r"(a1), "r"(a2), "r"(a3), "r"(b0), "r"(b1));
            }
        }
        __syncthreads();
    }

    float as_v[16], ad_v[16];
#pragma unroll
    for (int nt = 0; nt < 8; nt++) {
        as_v[nt * 2 + 0] = att_src[nt * 8 + 2 * c + 0];
        as_v[nt * 2 + 1] = att_src[nt * 8 + 2 * c + 1];
        ad_v[nt * 2 + 0] = att_dst[nt * 8 + 2 * c + 0];
        ad_v[nt * 2 + 1] = att_dst[nt * 8 + 2 * c + 1];
    }

    float ps1 = 0.f, pd1 = 0.f, ps2 = 0.f, pd2 = 0.f;
#pragma unroll
    for (int nt = 0; nt < 8; nt++) {
        ps1 += d[nt][0] * as_v[2 * nt] + d[nt][1] * as_v[2 * nt + 1];
        pd1 += d[nt][0] * ad_v[2 * nt] + d[nt][1] * ad_v[2 * nt + 1];
        ps2 += d[nt][2] * as_v[2 * nt] + d[nt][3] * as_v[2 * nt + 1];
        pd2 += d[nt][2] * ad_v[2 * nt] + d[nt][3] * ad_v[2 * nt + 1];
    }
#pragma unroll
    for (int o = 1; o < 4; o <<= 1) {
        ps1 += __shfl_xor_sync(0xffffffffu, ps1, o);
        pd1 += __shfl_xor_sync(0xffffffffu, pd1, o);
        ps2 += __shfl_xor_sync(0xffffffffu, ps2, o);
        pd2 += __shfl_xor_sync(0xffffffffu, pd2, o);
    }

    int r1 = row0 + wrow + g;
    int r2 = r1 + 8;
    if (c == 0) {
        if (r1 < n) { g_asrc[r1] = ps1; g_adst[r1] = pd1; }
        if (r2 < n) { g_asrc[r2] = ps2; g_adst[r2] = pd2; }
    }
    if (r1 < n) {
#pragma unroll
        for (int nt = 0; nt < 8; nt++) {
            __half2 h = __float22half2_rn(make_float2(d[nt][0], d[nt][1]));
            *reinterpret_cast<__half2*>(&g_hh[(size_t)r1 * FOUT + nt * 8 + 2 * c]) = h;
        }
    }
    if (r2 < n) {
#pragma unroll
        for (int nt = 0; nt < 8; nt++) {
            __half2 h = __float22half2_rn(make_float2(d[nt][2], d[nt][3]));
            *reinterpret_cast<__half2*>(&g_hh[(size_t)r2 * FOUT + nt * 8 + 2 * c]) = h;
        }
    }
}

// ---------------- kernel 6: gather aggregation, branchless fixed-32 batches ----------------
// Padding lanes: p=0 (their gathers contribute nothing); g_src's zero-init tail keeps
// addresses in range. Inner loop is a compile-time 16-iteration unroll -> batched LDGs.
__global__ __launch_bounds__(256) void aggregate_kernel(
    float* __restrict__ out, const float* __restrict__ bias, int n)
{
    __shared__ int   s_s[8][32];
    __shared__ float p_s[8][32];

    int w = threadIdx.x >> 5;
    int lane = threadIdx.x & 31;
    int half = lane >> 4;
    int l = lane & 15;
    int node = blockIdx.x * 8 + w;
    if (node >= n) return;

    int rs = g_off[node];
    int re = g_off[node + 1];
    float adst = g_adst[node];

    float4 acc = make_float4(0.f, 0.f, 0.f, 0.f);
    float dsum = 0.f;

    for (int base = rs; base < re; base += 32) {
        int idx = base + lane;
        bool ok = idx < re;
        int s = g_src[idx];               // padded array: safe even when !ok
        float v = g_asrc[s] + adst;
        v = v > 0.f ? v : 0.2f * v;
        float p = ok ? __expf(v) : 0.f;
        dsum += p;
        s_s[w][lane] = s;
        p_s[w][lane] = p;
        __syncwarp();
#pragma unroll
        for (int t = 0; t < 32; t += 2) {  // fixed trip count: loads get batched
            int tt = t + half;
            int st = s_s[w][tt];
            float pt = p_s[w][tt];
            uint2 hv = *reinterpret_cast<const uint2*>(&g_hh[(size_t)st * FOUT + l * 4]);
            float2 f01 = __half22float2(*reinterpret_cast<__half2*>(&hv.x));
            float2 f23 = __half22float2(*reinterpret_cast<__half2*>(&hv.y));
            acc.x += pt * f01.x; acc.y += pt * f01.y;
            acc.z += pt * f23.x; acc.w += pt * f23.y;
        }
        __syncwarp();
    }

    // self-loop (half 0 only)
    if (half == 0) {
        float v = g_asrc[node] + adst;
        v = v > 0.f ? v : 0.2f * v;
        float p = __expf(v);
        if (l == 0) dsum += p;
        uint2 hv = *reinterpret_cast<const uint2*>(&g_hh[(size_t)node * FOUT + l * 4]);
        float2 f01 = __half22float2(*reinterpret_cast<__half2*>(&hv.x));
        float2 f23 = __half22float2(*reinterpret_cast<__half2*>(&hv.y));
        acc.x += p * f01.x; acc.y += p * f01.y;
        acc.z += p * f23.x; acc.w += p * f23.y;
    }

#pragma unroll
    for (int o = 16; o > 0; o >>= 1)
        dsum += __shfl_xor_sync(0xffffffffu, dsum, o);

    acc.x += __shfl_down_sync(0xffffffffu, acc.x, 16);
    acc.y += __shfl_down_sync(0xffffffffu, acc.y, 16);
    acc.z += __shfl_down_sync(0xffffffffu, acc.z, 16);
    acc.w += __shfl_down_sync(0xffffffffu, acc.w, 16);

    if (half == 0) {
        float inv = 1.0f / (dsum + 1e-16f);
        float4 b = reinterpret_cast<const float4*>(bias)[l];
        reinterpret_cast<float4*>(out)[(size_t)node * 16 + l] =
            make_float4(acc.x * inv + b.x, acc.y * inv + b.y,
                        acc.z * inv + b.z, acc.w * inv + b.w);
    }
}

// ---------------- launch: fork GEMM ∥ CSR build, join before aggregate ----------------
extern "C" void kernel_launch(void* const* d_in, const int* in_sizes, int n_in,
                              void* d_out, int out_size) {
    const float* x       = (const float*)d_in[0];
    const int*   ei      = (const int*)d_in[1];
    const float* W       = (const float*)d_in[2];
    const float* att_src = (const float*)d_in[3];
    const float* att_dst = (const float*)d_in[4];
    const float* bias    = (const float*)d_in[5];
    float* out = (float*)d_out;

    int n = in_sizes[0] / KTOT;   // 100000
    int e = in_sizes[1] / 2;      // 3200000

    static cudaStream_t s2 = nullptr;
    static cudaEvent_t evFork = nullptr, evJoin = nullptr;
    if (s2 == nullptr) {
        cudaStreamCreateWithFlags(&s2, cudaStreamNonBlocking);
        cudaEventCreateWithFlags(&evFork, cudaEventDisableTiming);
        cudaEventCreateWithFlags(&evJoin, cudaEventDisableTiming);
    }

    cudaEventRecord(evFork, 0);
    cudaStreamWaitEvent(s2, evFork, 0);
    gemm_tc<<<(n + GB_ROWS - 1) / GB_ROWS, 256, 0, s2>>>(x, W, att_src, att_dst, n);
    cudaEventRecord(evJoin, s2);

    int nq = e / 4 + 4;
    zero_cnt<<<(n + 255) / 256, 256>>>(n, e);
    hist_kernel<<<(nq + 255) / 256, 256>>>(ei, e);
    scan_p1<<<NB, SCAN_B>>>(n);
    scan_p3<<<NB, SCAN_B>>>(n);
    scatter_kernel<<<(nq + 255) / 256, 256>>>(ei, e);

    cudaStreamWaitEvent(0, evJoin, 0);

    aggregate_kernel<<<(n + 7) / 8, 256>>>(out, bias, n);
}